// round 1
// baseline (speedup 1.0000x reference)
#include <cuda_runtime.h>
#include <cuda_bf16.h>
#include <math.h>

// GCN 2-layer: out = tanh(GCNConv(x,W1,b1)) @ W2 + b2
// N=50000 nodes, E=640000 edges, D_in=D_hid=D_out=128.
//
// Decomposition:
//   deg[i]  = 1 + #edges(dst=i);  dinv[i] = rsqrt(deg[i])
//   hs      = rowscale(dinv) * (x @ W1)            (GEMM1, epilogue scale)
//   acc[i]  = hs[i] + sum_{e:dst=i} hs[src(e)]     (self-loop init + edge atomics)
//   t[i,k]  = tanh(dinv[i]*acc[i,k] + b1[k])       (fused into GEMM2 smem load)
//   out     = t @ W2 + b2                          (GEMM2)

#define N_NODES 50000
#define DIM     128

__device__ float g_h  [(size_t)N_NODES * DIM];  // hs = dinv[i] * (x@W1)[i]
__device__ float g_agg[(size_t)N_NODES * DIM];  // accumulator (init = hs, then edge adds)
__device__ float g_deg [N_NODES];
__device__ float g_dinv[N_NODES];

// ---------------------------------------------------------------- degree prep

__global__ void k_deg_init() {
    int i = blockIdx.x * blockDim.x + threadIdx.x;
    if (i < N_NODES) g_deg[i] = 1.0f;  // self-loop
}

__global__ void k_deg_count(const int* __restrict__ ei, int E) {
    int e = blockIdx.x * blockDim.x + threadIdx.x;
    if (e < E) atomicAdd(&g_deg[ei[E + e]], 1.0f);  // dst row of edge_index
}

__global__ void k_dinv() {
    int i = blockIdx.x * blockDim.x + threadIdx.x;
    if (i < N_NODES) g_dinv[i] = rsqrtf(g_deg[i]);
}

// ---------------------------------------------------------------- GEMM 1
// hs = rowscale(dinv) * (x @ W1); also initializes g_agg = hs (self-loop term).
// Block tile 64x128, thread tile 4x8, K chunked by 32.

__global__ __launch_bounds__(256) void k_gemm1(const float* __restrict__ x,
                                               const float* __restrict__ W) {
    __shared__ float xs[64][33];
    __shared__ float ws[32][128];
    const int tx = threadIdx.x & 15;
    const int ty = threadIdx.x >> 4;
    const int row0 = blockIdx.x * 64;

    float acc[4][8];
#pragma unroll
    for (int r = 0; r < 4; r++)
#pragma unroll
        for (int c = 0; c < 8; c++) acc[r][c] = 0.0f;

    for (int kt = 0; kt < DIM; kt += 32) {
#pragma unroll
        for (int i = 0; i < 8; i++) {          // 64x32 x-tile
            int idx = threadIdx.x + i * 256;
            int r = idx >> 5, k = idx & 31;
            int gr = row0 + r;
            xs[r][k] = (gr < N_NODES) ? x[(size_t)gr * DIM + kt + k] : 0.0f;
        }
#pragma unroll
        for (int i = 0; i < 16; i++) {         // 32x128 W-tile
            int idx = threadIdx.x + i * 256;
            int k = idx >> 7, n = idx & 127;
            ws[k][n] = W[(size_t)(kt + k) * DIM + n];
        }
        __syncthreads();
#pragma unroll
        for (int kk = 0; kk < 32; kk++) {
            float a[4], b[8];
#pragma unroll
            for (int r = 0; r < 4; r++) a[r] = xs[ty * 4 + r][kk];
#pragma unroll
            for (int c = 0; c < 8; c++) b[c] = ws[kk][tx + c * 16];
#pragma unroll
            for (int r = 0; r < 4; r++)
#pragma unroll
                for (int c = 0; c < 8; c++) acc[r][c] = fmaf(a[r], b[c], acc[r][c]);
        }
        __syncthreads();
    }

#pragma unroll
    for (int r = 0; r < 4; r++) {
        int gr = row0 + ty * 4 + r;
        if (gr < N_NODES) {
            float s = g_dinv[gr];
#pragma unroll
            for (int c = 0; c < 8; c++) {
                int col = tx + c * 16;
                float v = s * acc[r][c];
                g_h  [(size_t)gr * DIM + col] = v;
                g_agg[(size_t)gr * DIM + col] = v;  // self-loop contribution
            }
        }
    }
}

// ---------------------------------------------------------------- edge agg
// One warp per edge: float4 gather of hs[src], vector RED into acc[dst].

__device__ __forceinline__ void red_add_f32x4(float* p, float4 v) {
    asm volatile("red.global.add.v4.f32 [%0], {%1,%2,%3,%4};"
                 :: "l"(p), "f"(v.x), "f"(v.y), "f"(v.z), "f"(v.w) : "memory");
}

__global__ __launch_bounds__(256) void k_edge(const int* __restrict__ ei, int E) {
    int warp = (blockIdx.x * blockDim.x + threadIdx.x) >> 5;
    int lane = threadIdx.x & 31;
    if (warp >= E) return;
    int src = ei[warp];
    int dst = ei[E + warp];
    const float4* hrow = (const float4*)(g_h + (size_t)src * DIM);
    float4 v = hrow[lane];                         // 32 lanes x 16B = 512B row
    float* orow = g_agg + (size_t)dst * DIM + lane * 4;
    red_add_f32x4(orow, v);
}

// ---------------------------------------------------------------- GEMM 2
// out = tanh(rowscale(dinv)*acc + b1) @ W2 + b2; tanh fused into smem load.

__global__ __launch_bounds__(256) void k_gemm2(const float* __restrict__ W,
                                               const float* __restrict__ b1,
                                               const float* __restrict__ b2,
                                               float* __restrict__ out) {
    __shared__ float xs[64][33];
    __shared__ float ws[32][128];
    const int tx = threadIdx.x & 15;
    const int ty = threadIdx.x >> 4;
    const int row0 = blockIdx.x * 64;

    float acc[4][8];
#pragma unroll
    for (int r = 0; r < 4; r++)
#pragma unroll
        for (int c = 0; c < 8; c++) acc[r][c] = 0.0f;

    for (int kt = 0; kt < DIM; kt += 32) {
#pragma unroll
        for (int i = 0; i < 8; i++) {
            int idx = threadIdx.x + i * 256;
            int r = idx >> 5, k = idx & 31;
            int gr = row0 + r;
            float t = 0.0f;
            if (gr < N_NODES) {
                float v = g_agg[(size_t)gr * DIM + kt + k];
                t = tanhf(g_dinv[gr] * v + b1[kt + k]);
            }
            xs[r][k] = t;
        }
#pragma unroll
        for (int i = 0; i < 16; i++) {
            int idx = threadIdx.x + i * 256;
            int k = idx >> 7, n = idx & 127;
            ws[k][n] = W[(size_t)(kt + k) * DIM + n];
        }
        __syncthreads();
#pragma unroll
        for (int kk = 0; kk < 32; kk++) {
            float a[4], b[8];
#pragma unroll
            for (int r = 0; r < 4; r++) a[r] = xs[ty * 4 + r][kk];
#pragma unroll
            for (int c = 0; c < 8; c++) b[c] = ws[kk][tx + c * 16];
#pragma unroll
            for (int r = 0; r < 4; r++)
#pragma unroll
                for (int c = 0; c < 8; c++) acc[r][c] = fmaf(a[r], b[c], acc[r][c]);
        }
        __syncthreads();
    }

#pragma unroll
    for (int r = 0; r < 4; r++) {
        int gr = row0 + ty * 4 + r;
        if (gr < N_NODES) {
#pragma unroll
            for (int c = 0; c < 8; c++) {
                int col = tx + c * 16;
                out[(size_t)gr * DIM + col] = acc[r][c] + b2[col];
            }
        }
    }
}

// ---------------------------------------------------------------- launch

extern "C" void kernel_launch(void* const* d_in, const int* in_sizes, int n_in,
                              void* d_out, int out_size) {
    const float* x  = (const float*)d_in[0];
    const int*   ei = (const int*)  d_in[1];
    const float* W1 = (const float*)d_in[2];
    const float* b1 = (const float*)d_in[3];
    const float* W2 = (const float*)d_in[4];
    const float* b2 = (const float*)d_in[5];
    float* out = (float*)d_out;

    const int E = in_sizes[1] / 2;

    k_deg_init <<<(N_NODES + 255) / 256, 256>>>();
    k_deg_count<<<(E + 255) / 256, 256>>>(ei, E);
    k_dinv     <<<(N_NODES + 255) / 256, 256>>>();
    k_gemm1    <<<(N_NODES + 63) / 64, 256>>>(x, W1);
    k_edge     <<<(E + 7) / 8, 256>>>(ei, E);       // 8 warps/block, 1 warp/edge
    k_gemm2    <<<(N_NODES + 63) / 64, 256>>>(W2, b1, b2, out);
}

// round 2
// speedup vs baseline: 1.0019x; 1.0019x over previous
#include <cuda_runtime.h>
#include <cuda_bf16.h>
#include <math.h>

// GCN 2-layer: out = tanh(GCNConv(x,W1,b1)) @ W2 + b2
// N=50000 nodes, E=640000 edges, D_in=D_hid=D_out=128.
//
// Decomposition:
//   deg[i]  = 1 + #edges(dst=i);  dinv[i] = rsqrt(deg[i])
//   hs      = rowscale(dinv) * (x @ W1)            (GEMM1, epilogue scale)
//   acc[i]  = hs[i] + sum_{e:dst=i} hs[src(e)]     (self-loop init + edge atomics)
//   t[i,k]  = tanh(dinv[i]*acc[i,k] + b1[k])       (fused into GEMM2 smem load)
//   out     = t @ W2 + b2                          (GEMM2)

#define N_NODES 50000
#define DIM     128

__device__ float g_h  [(size_t)N_NODES * DIM];  // hs = dinv[i] * (x@W1)[i]
__device__ float g_agg[(size_t)N_NODES * DIM];  // accumulator (init = hs, then edge adds)
__device__ float g_deg [N_NODES];
__device__ float g_dinv[N_NODES];

// ---------------------------------------------------------------- degree prep

__global__ void k_deg_init() {
    int i = blockIdx.x * blockDim.x + threadIdx.x;
    if (i < N_NODES) g_deg[i] = 1.0f;  // self-loop
}

__global__ void k_deg_count(const int* __restrict__ ei, int E) {
    int e = blockIdx.x * blockDim.x + threadIdx.x;
    if (e < E) atomicAdd(&g_deg[ei[E + e]], 1.0f);  // dst row of edge_index
}

__global__ void k_dinv() {
    int i = blockIdx.x * blockDim.x + threadIdx.x;
    if (i < N_NODES) g_dinv[i] = rsqrtf(g_deg[i]);
}

// ---------------------------------------------------------------- GEMM 1
// hs = rowscale(dinv) * (x @ W1); also initializes g_agg = hs (self-loop term).
// Block tile 64x128, thread tile 4x8, K chunked by 32.

__global__ __launch_bounds__(256) void k_gemm1(const float* __restrict__ x,
                                               const float* __restrict__ W) {
    __shared__ float xs[64][33];
    __shared__ float ws[32][128];
    const int tx = threadIdx.x & 15;
    const int ty = threadIdx.x >> 4;
    const int row0 = blockIdx.x * 64;

    float acc[4][8];
#pragma unroll
    for (int r = 0; r < 4; r++)
#pragma unroll
        for (int c = 0; c < 8; c++) acc[r][c] = 0.0f;

    for (int kt = 0; kt < DIM; kt += 32) {
#pragma unroll
        for (int i = 0; i < 8; i++) {          // 64x32 x-tile
            int idx = threadIdx.x + i * 256;
            int r = idx >> 5, k = idx & 31;
            int gr = row0 + r;
            xs[r][k] = (gr < N_NODES) ? x[(size_t)gr * DIM + kt + k] : 0.0f;
        }
#pragma unroll
        for (int i = 0; i < 16; i++) {         // 32x128 W-tile
            int idx = threadIdx.x + i * 256;
            int k = idx >> 7, n = idx & 127;
            ws[k][n] = W[(size_t)(kt + k) * DIM + n];
        }
        __syncthreads();
#pragma unroll
        for (int kk = 0; kk < 32; kk++) {
            float a[4], b[8];
#pragma unroll
            for (int r = 0; r < 4; r++) a[r] = xs[ty * 4 + r][kk];
#pragma unroll
            for (int c = 0; c < 8; c++) b[c] = ws[kk][tx + c * 16];
#pragma unroll
            for (int r = 0; r < 4; r++)
#pragma unroll
                for (int c = 0; c < 8; c++) acc[r][c] = fmaf(a[r], b[c], acc[r][c]);
        }
        __syncthreads();
    }

#pragma unroll
    for (int r = 0; r < 4; r++) {
        int gr = row0 + ty * 4 + r;
        if (gr < N_NODES) {
            float s = g_dinv[gr];
#pragma unroll
            for (int c = 0; c < 8; c++) {
                int col = tx + c * 16;
                float v = s * acc[r][c];
                g_h  [(size_t)gr * DIM + col] = v;
                g_agg[(size_t)gr * DIM + col] = v;  // self-loop contribution
            }
        }
    }
}

// ---------------------------------------------------------------- edge agg
// One warp per edge: float4 gather of hs[src], vector RED into acc[dst].

__device__ __forceinline__ void red_add_f32x4(float* p, float4 v) {
    asm volatile("red.global.add.v4.f32 [%0], {%1,%2,%3,%4};"
                 :: "l"(p), "f"(v.x), "f"(v.y), "f"(v.z), "f"(v.w) : "memory");
}

__global__ __launch_bounds__(256) void k_edge(const int* __restrict__ ei, int E) {
    int warp = (blockIdx.x * blockDim.x + threadIdx.x) >> 5;
    int lane = threadIdx.x & 31;
    if (warp >= E) return;
    int src = ei[warp];
    int dst = ei[E + warp];
    const float4* hrow = (const float4*)(g_h + (size_t)src * DIM);
    float4 v = hrow[lane];                         // 32 lanes x 16B = 512B row
    float* orow = g_agg + (size_t)dst * DIM + lane * 4;
    red_add_f32x4(orow, v);
}

// ---------------------------------------------------------------- GEMM 2
// out = tanh(rowscale(dinv)*acc + b1) @ W2 + b2; tanh fused into smem load.

__global__ __launch_bounds__(256) void k_gemm2(const float* __restrict__ W,
                                               const float* __restrict__ b1,
                                               const float* __restrict__ b2,
                                               float* __restrict__ out) {
    __shared__ float xs[64][33];
    __shared__ float ws[32][128];
    const int tx = threadIdx.x & 15;
    const int ty = threadIdx.x >> 4;
    const int row0 = blockIdx.x * 64;

    float acc[4][8];
#pragma unroll
    for (int r = 0; r < 4; r++)
#pragma unroll
        for (int c = 0; c < 8; c++) acc[r][c] = 0.0f;

    for (int kt = 0; kt < DIM; kt += 32) {
#pragma unroll
        for (int i = 0; i < 8; i++) {
            int idx = threadIdx.x + i * 256;
            int r = idx >> 5, k = idx & 31;
            int gr = row0 + r;
            float t = 0.0f;
            if (gr < N_NODES) {
                float v = g_agg[(size_t)gr * DIM + kt + k];
                t = tanhf(g_dinv[gr] * v + b1[kt + k]);
            }
            xs[r][k] = t;
        }
#pragma unroll
        for (int i = 0; i < 16; i++) {
            int idx = threadIdx.x + i * 256;
            int k = idx >> 7, n = idx & 127;
            ws[k][n] = W[(size_t)(kt + k) * DIM + n];
        }
        __syncthreads();
#pragma unroll
        for (int kk = 0; kk < 32; kk++) {
            float a[4], b[8];
#pragma unroll
            for (int r = 0; r < 4; r++) a[r] = xs[ty * 4 + r][kk];
#pragma unroll
            for (int c = 0; c < 8; c++) b[c] = ws[kk][tx + c * 16];
#pragma unroll
            for (int r = 0; r < 4; r++)
#pragma unroll
                for (int c = 0; c < 8; c++) acc[r][c] = fmaf(a[r], b[c], acc[r][c]);
        }
        __syncthreads();
    }

#pragma unroll
    for (int r = 0; r < 4; r++) {
        int gr = row0 + ty * 4 + r;
        if (gr < N_NODES) {
#pragma unroll
            for (int c = 0; c < 8; c++) {
                int col = tx + c * 16;
                out[(size_t)gr * DIM + col] = acc[r][c] + b2[col];
            }
        }
    }
}

// ---------------------------------------------------------------- launch

extern "C" void kernel_launch(void* const* d_in, const int* in_sizes, int n_in,
                              void* d_out, int out_size) {
    const float* x  = (const float*)d_in[0];
    const int*   ei = (const int*)  d_in[1];
    const float* W1 = (const float*)d_in[2];
    const float* b1 = (const float*)d_in[3];
    const float* W2 = (const float*)d_in[4];
    const float* b2 = (const float*)d_in[5];
    float* out = (float*)d_out;

    const int E = in_sizes[1] / 2;

    k_deg_init <<<(N_NODES + 255) / 256, 256>>>();
    k_deg_count<<<(E + 255) / 256, 256>>>(ei, E);
    k_dinv     <<<(N_NODES + 255) / 256, 256>>>();
    k_gemm1    <<<(N_NODES + 63) / 64, 256>>>(x, W1);
    k_edge     <<<(E + 7) / 8, 256>>>(ei, E);       // 8 warps/block, 1 warp/edge
    k_gemm2    <<<(N_NODES + 63) / 64, 256>>>(W2, b1, b2, out);
}